// round 17
// baseline (speedup 1.0000x reference)
#include <cuda_runtime.h>
#include <cuda_bf16.h>
#include <cstdint>
#include <math.h>

// ----------------------------------------------------------------------------
// DLRM forward. R15->R16:
//  * All GEMM operands pre-split into packed bf16 (hi,lo)-pair "planes"
//    (uint2 per k-pair). Weights + x converted once per launch; GEMM epilogues
//    write planes directly; interact packs R planes. K-loop has no cvt/STS.
//  * GEMM k-loop: cp.async (LDGSTS) 3-stage pipeline, one barrier + one
//    wait_group per iter, 24 m16n8k16 bf16 MMAs per iter (3-term split).
// ----------------------------------------------------------------------------

#define BB      8192
#define NTAB    26
#define LBAG    10
#define VROWS   200000
#define DD      64
#define TROW    1728        // 27*64 floats per batch row of T
#define NEMB    (NTAB * (BB / 16))
#define KP2_OF(K) ((((K) + 15) / 16) * 8)   // padded k-pairs per row

// ---------------- scratch (device globals: no allocs allowed) ----------------
__device__ __align__(16) float g_T [BB * TROW];   // [B][27][64]
__device__ __align__(16) float g_h2[BB * 256];    // top2 out (fp32, for top3)
__device__ __align__(16) uint2 g_xp  [BB * 8];        // x planes (K=13 -> 8 pairs)
__device__ __align__(16) uint2 g_bw1p[512 * 8];
__device__ __align__(16) uint2 g_bw2p[256 * 256];
__device__ __align__(16) uint2 g_bw3p[64 * 128];
__device__ __align__(16) uint2 g_tw1p[512 * 208];
__device__ __align__(16) uint2 g_tw2p[256 * 256];
__device__ __align__(16) uint2 g_h1p [BB * 256];      // bot1/top1 out planes
__device__ __align__(16) uint2 g_h2p [BB * 128];      // bot2 out planes
__device__ __align__(16) uint2 g_Rp  [BB * 208];      // interaction out planes
__device__ int g_idx64;

// ---------------- helpers ----------------
__device__ __forceinline__ void mma_bf16(float* d, const uint32_t* a, const uint32_t* b) {
    asm volatile(
        "mma.sync.aligned.m16n8k16.row.col.f32.bf16.bf16.f32 "
        "{%0,%1,%2,%3}, {%4,%5,%6,%7}, {%8,%9}, {%0,%1,%2,%3};\n"
        : "+f"(d[0]), "+f"(d[1]), "+f"(d[2]), "+f"(d[3])
        : "r"(a[0]), "r"(a[1]), "r"(a[2]), "r"(a[3]), "r"(b[0]), "r"(b[1]));
}

// split k-pair (v0 even-k, v1 odd-k) into packed bf16 hi/lo words
__device__ __forceinline__ void split_pair(float v0, float v1,
                                           uint32_t& hiw, uint32_t& low)
{
    const __nv_bfloat16 h0 = __float2bfloat16_rn(v0);
    const __nv_bfloat16 h1 = __float2bfloat16_rn(v1);
    const float r0 = v0 - __bfloat162float(h0);
    const float r1 = v1 - __bfloat162float(h1);
    const __nv_bfloat162 hp = __nv_bfloat162(h0, h1);
    const __nv_bfloat162 lp = __floats2bfloat162_rn(r0, r1);
    hiw = *reinterpret_cast<const uint32_t*>(&hp);
    low = *reinterpret_cast<const uint32_t*>(&lp);
}

__device__ __forceinline__ void cp16(uint32_t smem_dst, const void* gsrc) {
    asm volatile("cp.async.cg.shared.global [%0], [%1], 16;" :: "r"(smem_dst), "l"(gsrc));
}

// ---------------- conversion (+ index detect) kernel ------------------------
struct ConvParams {
    const float* src[6];
    uint2*       dst[6];
    int K[6], KP2[6], rows[6];
    int start[7];               // cumulative block offsets
    const unsigned int* idxProbe;
    int nConvBlocks;
};

__global__ void conv_kernel(ConvParams P)
{
    if ((int)blockIdx.x >= P.nConvBlocks) {
        if (threadIdx.x == 0) {
            int f = 1;
            for (int i = 0; i < 128; i++)
                if (P.idxProbe[2 * i + 1] != 0u) { f = 0; break; }
            g_idx64 = f;
        }
        return;
    }
    int j = 0;
    while ((int)blockIdx.x >= P.start[j + 1]) j++;
    const int K = P.K[j], KP2 = P.KP2[j];
    const long long tot = (long long)P.rows[j] * KP2;
    long long p = (long long)((int)blockIdx.x - P.start[j]) * 2048 + threadIdx.x * 8;
    #pragma unroll
    for (int u = 0; u < 8; u++, p++) {
        if (p < tot) {
            const int row = (int)(p / KP2);
            const int c   = (int)(p % KP2);
            const int k0 = 2 * c, k1 = 2 * c + 1;
            const float v0 = (k0 < K) ? P.src[j][(size_t)row * K + k0] : 0.0f;
            const float v1 = (k1 < K) ? P.src[j][(size_t)row * K + k1] : 0.0f;
            uint32_t h, l; split_pair(v0, v1, h, l);
            P.dst[j][p] = make_uint2(h, l);
        }
    }
}

// ---------------- embedding bag block (device side) -------------------------
__device__ __forceinline__ void embed_block(int e, const void* __restrict__ lSi,
                                            const float* __restrict__ emb)
{
    const int c   = threadIdx.x & 15;
    const int bag = threadIdx.x >> 4;
    const int t   = e >> 9;
    const int b   = ((e & 511) << 4) + bag;

    const float4* tab = reinterpret_cast<const float4*>(emb)
                      + (size_t)t * (size_t)(VROWS * (DD / 4));
    const long long ibase = (long long)t * (BB * LBAG) + (long long)b * LBAG;

    int idx[LBAG];
    if (g_idx64) {
        const long long* I = reinterpret_cast<const long long*>(lSi);
        #pragma unroll
        for (int j = 0; j < LBAG; j++) idx[j] = (int)I[ibase + j];
    } else {
        const int* I = reinterpret_cast<const int*>(lSi);
        #pragma unroll
        for (int j = 0; j < LBAG; j++) idx[j] = I[ibase + j];
    }

    float4 acc = make_float4(0.f, 0.f, 0.f, 0.f);
    #pragma unroll
    for (int j = 0; j < LBAG; j++) {
        const float4 v = __ldg(&tab[(size_t)idx[j] * (DD / 4) + c]);
        acc.x += v.x; acc.y += v.y; acc.z += v.z; acc.w += v.w;
    }
    reinterpret_cast<float4*>(g_T)[(size_t)b * (TROW / 4) + (1 + t) * (DD / 4) + c] = acc;
}

// ---------------- fused GEMM (+ optional embed blocks) ----------------------
// C = relu(A[8192,K] @ W[M,K]^T + bias), operands as packed bf16 plane pairs.
// Block tile 128x64, BK=16, 256 thr = 8 warps (4m x 2n), warp tile 32x32.
// 3-stage cp.async pipeline; smem row stride 10 uint2 (16B-aligned, ~2-way).
// Output: planes (Cp,cp2) if Cp!=null else fp32 (Cf,ldc).
__global__ __launch_bounds__(256)
void fused_gemm_embed(const uint2* __restrict__ Ap, int ap2,
                      const uint2* __restrict__ Wp, int wp2,
                      int nkt,
                      const float* __restrict__ bias,
                      float* __restrict__ Cf, int ldc,
                      uint2* __restrict__ Cp, int cp2,
                      int gridGx, int nGemm,
                      const void* __restrict__ lSi,
                      const float* __restrict__ emb,
                      int embBase)
{
    if ((int)blockIdx.x >= nGemm) {
        embed_block((int)blockIdx.x - nGemm + embBase, lSi, emb);
        return;
    }

    __shared__ uint2 As[3][128 * 10];
    __shared__ uint2 Ws[3][64 * 10];

    const int tid  = threadIdx.x;
    const int warp = tid >> 5;
    const int lane = tid & 31;
    const int wm   = warp & 3;
    const int wn   = warp >> 2;
    const int gid  = lane >> 2;
    const int tig  = lane & 3;
    const int ch   = tid & 3;        // 16B chunk (pairs 2ch, 2ch+1)
    const int r0   = tid >> 2;       // 0..63

    const int bx = (int)blockIdx.x % gridGx;
    const int by = (int)blockIdx.x / gridGx;
    const size_t rowBase = (size_t)by * 128;
    const int colBase = bx * 64;

    const size_t aRow0 = (rowBase + r0) * (size_t)ap2;
    const size_t aRow1 = aRow0 + (size_t)64 * ap2;
    const size_t wRow  = (size_t)(colBase + r0) * (size_t)wp2;

    const uint32_t asBase = (uint32_t)__cvta_generic_to_shared(&As[0][0]);
    const uint32_t wsBase = (uint32_t)__cvta_generic_to_shared(&Ws[0][0]);

    auto issue = [&](int kt, int s) {
        if (kt < nkt) {
            const int ko = kt * 8 + 2 * ch;
            cp16(asBase + (uint32_t)(s * 1280 + r0 * 10 + 2 * ch) * 8,        Ap + aRow0 + ko);
            cp16(asBase + (uint32_t)(s * 1280 + (r0 + 64) * 10 + 2 * ch) * 8, Ap + aRow1 + ko);
            cp16(wsBase + (uint32_t)(s * 640 + r0 * 10 + 2 * ch) * 8,         Wp + wRow + ko);
        }
        asm volatile("cp.async.commit_group;" ::: "memory");
    };

    float acc[2][4][4];
    #pragma unroll
    for (int mt = 0; mt < 2; mt++)
        #pragma unroll
        for (int nt = 0; nt < 4; nt++)
            #pragma unroll
            for (int q = 0; q < 4; q++) acc[mt][nt][q] = 0.0f;

    issue(0, 0);
    issue(1, 1);

    int s = 0;
    for (int kt = 0; kt < nkt; kt++) {
        asm volatile("cp.async.wait_group %0;" :: "n"(1) : "memory");
        __syncthreads();

        const uint2* as = As[s];
        const uint2* ws = Ws[s];

        uint32_t a_hi[2][4], a_lo[2][4];
        #pragma unroll
        for (int mt = 0; mt < 2; mt++) {
            const int r = wm * 32 + mt * 16 + gid;
            const uint2 P0 = as[r * 10 + tig];
            const uint2 P1 = as[(r + 8) * 10 + tig];
            const uint2 P2 = as[r * 10 + tig + 4];
            const uint2 P3 = as[(r + 8) * 10 + tig + 4];
            a_hi[mt][0] = P0.x; a_lo[mt][0] = P0.y;
            a_hi[mt][1] = P1.x; a_lo[mt][1] = P1.y;
            a_hi[mt][2] = P2.x; a_lo[mt][2] = P2.y;
            a_hi[mt][3] = P3.x; a_lo[mt][3] = P3.y;
        }
        uint32_t b_hi[4][2], b_lo[4][2];
        #pragma unroll
        for (int nt = 0; nt < 4; nt++) {
            const int n = wn * 32 + nt * 8 + gid;
            const uint2 Q0 = ws[n * 10 + tig];
            const uint2 Q1 = ws[n * 10 + tig + 4];
            b_hi[nt][0] = Q0.x; b_lo[nt][0] = Q0.y;
            b_hi[nt][1] = Q1.x; b_lo[nt][1] = Q1.y;
        }

        // issue tile kt+2 into stage (kt+2)%3 == stage of tile kt-1 (done by
        // all warps before this iteration's barrier)
        issue(kt + 2, (kt + 2) % 3);

        #pragma unroll
        for (int mt = 0; mt < 2; mt++)
            #pragma unroll
            for (int nt = 0; nt < 4; nt++) {
                mma_bf16(acc[mt][nt], a_hi[mt], b_hi[nt]);
                mma_bf16(acc[mt][nt], a_hi[mt], b_lo[nt]);
                mma_bf16(acc[mt][nt], a_lo[mt], b_hi[nt]);
            }

        s = (s + 1 == 3) ? 0 : s + 1;
    }

    // ---- epilogue: bias + relu; write planes or fp32 ----
    #pragma unroll
    for (int mt = 0; mt < 2; mt++)
        #pragma unroll
        for (int nt = 0; nt < 4; nt++) {
            const size_t row = rowBase + wm * 32 + mt * 16 + gid;
            const int col = colBase + wn * 32 + nt * 8 + 2 * tig;
            const float b0 = bias[col];
            const float b1 = bias[col + 1];
            const float v0 = fmaxf(acc[mt][nt][0] + b0, 0.0f);
            const float v1 = fmaxf(acc[mt][nt][1] + b1, 0.0f);
            const float v2 = fmaxf(acc[mt][nt][2] + b0, 0.0f);
            const float v3 = fmaxf(acc[mt][nt][3] + b1, 0.0f);
            if (Cp) {
                const int cp = col >> 1;
                uint32_t h, l;
                split_pair(v0, v1, h, l);
                Cp[row * cp2 + cp] = make_uint2(h, l);
                split_pair(v2, v3, h, l);
                Cp[(row + 8) * cp2 + cp] = make_uint2(h, l);
            } else {
                *reinterpret_cast<float2*>(&Cf[row * ldc + col])       = make_float2(v0, v1);
                *reinterpret_cast<float2*>(&Cf[(row + 8) * ldc + col]) = make_float2(v2, v3);
            }
        }
}

// ---------------- dot interaction -> R planes -------------------------------
__global__ void interact_kernel()
{
    __shared__ __align__(16) float Ts[27 * 68];
    __shared__ __align__(16) float Rs[416];
    const int b = blockIdx.x;
    const float4* Tb = reinterpret_cast<const float4*>(g_T + (size_t)b * TROW);
    float4* Ts4 = reinterpret_cast<float4*>(Ts);

    for (int g = threadIdx.x; g < TROW / 4; g += 128) {
        const int r = g >> 4;
        const int c = g & 15;
        Ts4[r * 17 + c] = Tb[g];
    }
    if (threadIdx.x == 0) Rs[415] = 0.0f;
    __syncthreads();

    if (threadIdx.x < 64) Rs[threadIdx.x] = Ts[threadIdx.x];   // row 0 = h

    for (int t = threadIdx.x; t < 91; t += 128) {
        int ti = (int)((sqrtf(8.0f * (float)t + 1.0f) - 1.0f) * 0.5f);
        while (ti * (ti + 1) / 2 > t) --ti;
        while ((ti + 1) * (ti + 2) / 2 <= t) ++ti;
        const int tj = t - ti * (ti + 1) / 2;
        const int i0 = 2 * ti + 1;
        const int j0 = 2 * tj;

        const float4* u0 = Ts4 + i0 * 17;
        const float4* u1 = u0 + 17;
        const float4* v0 = Ts4 + j0 * 17;
        const float4* v1 = v0 + 17;
        float s00 = 0.f, s01 = 0.f, s10 = 0.f, s11 = 0.f;
        #pragma unroll
        for (int k = 0; k < DD / 4; k++) {
            const float4 a0 = u0[k], a1 = u1[k], c0 = v0[k], c1 = v1[k];
            s00 += a0.x * c0.x + a0.y * c0.y + a0.z * c0.z + a0.w * c0.w;
            s01 += a0.x * c1.x + a0.y * c1.y + a0.z * c1.z + a0.w * c1.w;
            s10 += a1.x * c0.x + a1.y * c0.y + a1.z * c0.z + a1.w * c0.w;
            s11 += a1.x * c1.x + a1.y * c1.y + a1.z * c1.z + a1.w * c1.w;
        }
        const int bi0 = i0 * (i0 - 1) / 2;
        const int bi1 = i0 * (i0 + 1) / 2;
        Rs[64 + bi0 + j0] = s00;
        if (ti != tj) Rs[64 + bi0 + j0 + 1] = s01;
        Rs[64 + bi1 + j0]     = s10;
        Rs[64 + bi1 + j0 + 1] = s11;
    }
    __syncthreads();

    uint2* Rp = g_Rp + (size_t)b * 208;
    for (int cp = threadIdx.x; cp < 208; cp += 128) {
        uint32_t h, l;
        split_pair(Rs[2 * cp], Rs[2 * cp + 1], h, l);
        Rp[cp] = make_uint2(h, l);
    }
}

// ---------------- top layer 3: out[b] = sigmoid(dot(z2[b], w3) + b3) --------
__global__ void top3_kernel(const float* __restrict__ w3, const float* __restrict__ b3,
                            float* __restrict__ out)
{
    const int gwarp = (int)((blockIdx.x * blockDim.x + threadIdx.x) >> 5);
    const int lane  = threadIdx.x & 31;
    const float4* z = reinterpret_cast<const float4*>(g_h2) + (size_t)gwarp * 64;
    const float4* w = reinterpret_cast<const float4*>(w3);

    const float4 z0 = z[lane],      w0 = w[lane];
    const float4 z1 = z[lane + 32], w1 = w[lane + 32];
    float s = z0.x * w0.x + z0.y * w0.y + z0.z * w0.z + z0.w * w0.w
            + z1.x * w1.x + z1.y * w1.y + z1.z * w1.z + z1.w * w1.w;
    #pragma unroll
    for (int o = 16; o > 0; o >>= 1) s += __shfl_xor_sync(0xffffffffu, s, o);
    if (lane == 0) out[gwarp] = 1.0f / (1.0f + expf(-(s + b3[0])));
}

// ---------------- host ----------------
static void run_gemm(const uint2* Ap, int ap2, const uint2* Wp, int wp2, int K,
                     const float* bias, float* Cf, int ldc, uint2* Cp, int cp2,
                     int M, const void* lSi, const float* emb,
                     int embBase, int embCount)
{
    const int gridGx = M / 64;
    const int nGemm  = gridGx * (BB / 128);
    const int nkt    = (K + 15) / 16;
    fused_gemm_embed<<<nGemm + embCount, 256>>>(Ap, ap2, Wp, wp2, nkt, bias,
                                                Cf, ldc, Cp, cp2,
                                                gridGx, nGemm, lSi, emb, embBase);
}

extern "C" void kernel_launch(void* const* d_in, const int* in_sizes, int n_in,
                              void* d_out, int out_size)
{
    int IX_X, IX_LSI, IX_EMB, IX_BW1, IX_BB1, IX_BW2, IX_BB2, IX_BW3, IX_BB3;
    int IX_TW1, IX_TB1, IX_TW2, IX_TB2, IX_TW3, IX_TB3;
    if (in_sizes[0] == BB * 13) {
        IX_X = 0; IX_LSI = 1; IX_EMB = 3;
        IX_BW1 = 4;  IX_BB1 = 5;  IX_BW2 = 6;  IX_BB2 = 7;  IX_BW3 = 8;  IX_BB3 = 9;
        IX_TW1 = 10; IX_TB1 = 11; IX_TW2 = 12; IX_TB2 = 13; IX_TW3 = 14; IX_TB3 = 15;
    } else {
        IX_BW1 = 0; IX_BW2 = 1; IX_BW3 = 2; IX_BB1 = 3; IX_BB2 = 4; IX_BB3 = 5;
        IX_EMB = 6; IX_LSI = 7;
        IX_TW1 = 9; IX_TW2 = 10; IX_TW3 = 11; IX_TB1 = 12; IX_TB2 = 13; IX_TB3 = 14;
        IX_X = 15;
    }

    const float* x    = (const float*)d_in[IX_X];
    const void*  lSi  = d_in[IX_LSI];
    const float* emb  = (const float*)d_in[IX_EMB];
    const float* bw1  = (const float*)d_in[IX_BW1];
    const float* bb1  = (const float*)d_in[IX_BB1];
    const float* bw2  = (const float*)d_in[IX_BW2];
    const float* bb2  = (const float*)d_in[IX_BB2];
    const float* bw3  = (const float*)d_in[IX_BW3];
    const float* bb3  = (const float*)d_in[IX_BB3];
    const float* tw1  = (const float*)d_in[IX_TW1];
    const float* tb1  = (const float*)d_in[IX_TB1];
    const float* tw2  = (const float*)d_in[IX_TW2];
    const float* tb2  = (const float*)d_in[IX_TB2];
    const float* tw3  = (const float*)d_in[IX_TW3];
    const float* tb3  = (const float*)d_in[IX_TB3];
    float* out = (float*)d_out;

    float *T, *h2;
    uint2 *xp, *bw1p, *bw2p, *bw3p, *tw1p, *tw2p, *h1p, *h2p, *Rp;
    cudaGetSymbolAddress((void**)&T,    g_T);
    cudaGetSymbolAddress((void**)&h2,   g_h2);
    cudaGetSymbolAddress((void**)&xp,   g_xp);
    cudaGetSymbolAddress((void**)&bw1p, g_bw1p);
    cudaGetSymbolAddress((void**)&bw2p, g_bw2p);
    cudaGetSymbolAddress((void**)&bw3p, g_bw3p);
    cudaGetSymbolAddress((void**)&tw1p, g_tw1p);
    cudaGetSymbolAddress((void**)&tw2p, g_tw2p);
    cudaGetSymbolAddress((void**)&h1p,  g_h1p);
    cudaGetSymbolAddress((void**)&h2p,  g_h2p);
    cudaGetSymbolAddress((void**)&Rp,   g_Rp);

    // ---- conversion jobs: x + 5 weight matrices -> planes; plus detect ----
    ConvParams P;
    const float* srcs[6] = { x,  bw1, bw2, bw3, tw1, tw2 };
    uint2*       dsts[6] = { xp, bw1p, bw2p, bw3p, tw1p, tw2p };
    const int    Ks[6]   = { 13, 13, 512, 256, 415, 512 };
    const int    rws[6]  = { BB, 512, 256, 64, 512, 256 };
    P.start[0] = 0;
    for (int j = 0; j < 6; j++) {
        P.src[j] = srcs[j]; P.dst[j] = dsts[j];
        P.K[j] = Ks[j]; P.KP2[j] = KP2_OF(Ks[j]); P.rows[j] = rws[j];
        const long long pairs = (long long)rws[j] * P.KP2[j];
        P.start[j + 1] = P.start[j] + (int)((pairs + 2047) / 2048);
    }
    P.idxProbe = (const unsigned int*)lSi;
    P.nConvBlocks = P.start[6];
    conv_kernel<<<P.nConvBlocks + 1, 256>>>(P);

    // ---- bottom MLP fused with embedding-bag blocks ----
    const int E1 = 4438, E2 = 4437, E3 = NEMB - 4438 - 4437;
    run_gemm(xp,  8,   bw1p, 8,   13,  bb1, nullptr, 0, h1p, 256, 512, lSi, emb, 0,       E1);
    run_gemm(h1p, 256, bw2p, 256, 512, bb2, nullptr, 0, h2p, 128, 256, lSi, emb, E1,      E2);
    run_gemm(h2p, 128, bw3p, 128, 256, bb3, T, TROW, nullptr, 0,  64,  lSi, emb, E1 + E2, E3);

    // ---- dot interaction -> R planes ----
    interact_kernel<<<BB, 128>>>();

    // ---- top MLP ----
    run_gemm(Rp,  208, tw1p, 208, 415, tb1, nullptr, 0, h1p, 256, 512, lSi, emb, 0, 0);
    run_gemm(h1p, 256, tw2p, 256, 512, tb2, h2, 256,  nullptr, 0,  256, lSi, emb, 0, 0);

    // ---- final 256 -> 1 dot + sigmoid ----
    top3_kernel<<<BB / 8, 256>>>(tw3, tb3, out);
}